// round 16
// baseline (speedup 1.0000x reference)
#include <cuda_runtime.h>
#include <cuda_bf16.h>
#include <cuda_fp16.h>
#include <cstdint>
#include <math.h>

// Problem constants
static constexpr int B  = 4;
static constexpr int S  = 2048;
static constexpr int D  = 1024;
static constexpr int H  = 16;
static constexpr int DK = 64;
static constexpr int M  = B * S;      // 8192
static constexpr int K2 = 2 * D;      // 2048: fp16x2 concatenated K

// Scratch (__device__ globals; allocation forbidden)
__device__ __half g_Qh[(size_t)M * D];
__device__ __half g_Kh[(size_t)M * D];
__device__ __half g_Vh[(size_t)M * D];
__device__ __half g_Aq[(size_t)M * K2];      // q split; reused as attn X (stride D)
__device__ __half g_Ak[(size_t)M * K2];
__device__ __half g_Av[(size_t)M * D];       // v hi-only (stride D)
__device__ __half g_W2[2][(size_t)D * K2];   // Wq,Wk as [hi|hi] stride K2
__device__ __half g_WvH[(size_t)D * D];      // Wv hi-only, stride D
__device__ __half g_WoH[(size_t)D * D];      // Wo hi-only, stride D

__device__ __forceinline__ uint32_t smem_u32(const void* p) {
    uint32_t a;
    asm("{ .reg .u64 t; cvta.to.shared.u64 t, %1; cvt.u32.u64 %0, t; }" : "=r"(a) : "l"(p));
    return a;
}

__device__ __forceinline__ uint32_t ex2_h2(uint32_t x) {
    uint32_t y;
    asm("ex2.approx.f16x2 %0, %1;" : "=r"(y) : "r"(x));
    return y;
}

// ============================================================================
// Unified split kernel (one launch).
// y in {0,1}: q,k -> [hi|lo] stride K2.  y==2: v -> hi-only stride D.
// y==3: weights, blockIdx.x encodes (w, row); Wq/Wk -> [hi|hi], Wv/Wo -> hi.
// ============================================================================
struct SplitAllParams {
    const float* asrc[3]; __half* adst[3];
    const float* wsrc[4]; __half* wdst[4];
};

__global__ __launch_bounds__(256)
void split_all_kernel(SplitAllParams p)
{
    const int c = threadIdx.x * 4;
    const int y = blockIdx.y;
    if (y < 3) {
        const float* src = p.asrc[y];
        const int r = blockIdx.x;
        float4 x = *(const float4*)(src + (size_t)r * D + c);
        __align__(8) __half h[4];
        float xs[4] = {x.x, x.y, x.z, x.w};
        #pragma unroll
        for (int i = 0; i < 4; i++) h[i] = __float2half_rn(xs[i]);
        if (y < 2) {
            __align__(8) __half l[4];
            #pragma unroll
            for (int i = 0; i < 4; i++)
                l[i] = __float2half_rn(xs[i] - __half2float(h[i]));
            __half* drow = p.adst[y] + (size_t)r * K2;
            *(uint2*)(drow + c)     = *(uint2*)h;
            *(uint2*)(drow + D + c) = *(uint2*)l;
        } else {
            __half* drow = p.adst[2] + (size_t)r * D;
            *(uint2*)(drow + c) = *(uint2*)h;
        }
    } else {
        const int r = blockIdx.x;
        if (r >= 4 * D) return;
        const int w   = r >> 10;
        const int row = r & (D - 1);
        const float* src = p.wsrc[w];
        float4 x = *(const float4*)(src + (size_t)row * D + c);
        __align__(8) __half h[4];
        float xs[4] = {x.x, x.y, x.z, x.w};
        #pragma unroll
        for (int i = 0; i < 4; i++) h[i] = __float2half_rn(xs[i]);
        if (w < 2) {
            __half* drow = p.wdst[w] + (size_t)row * K2;
            *(uint2*)(drow + c)     = *(uint2*)h;
            *(uint2*)(drow + D + c) = *(uint2*)h;
        } else {
            __half* drow = p.wdst[w] + (size_t)row * D;
            *(uint2*)(drow + c) = *(uint2*)h;
        }
    }
}

// ============================================================================
// HMMA GEMM: 128x128 block, 4 warps, BK=64, 2-stage cp.async, 3 blocks/SM.
// Templated on KDIM. A and Wt row stride == KDIM.
// ============================================================================
static constexpr int BK64    = 64;
static constexpr int PADK    = 72;
static constexpr int ATILE_B = 128 * PADK * 2;          // 18432
static constexpr int STAGE_B = 2 * ATILE_B;             // 36864
static constexpr int GEMM_SMEM = 2 * STAGE_B;           // 73728 -> 3 blocks/SM

#define CP_ASYNC16(sm, gm) \
    asm volatile("cp.async.cg.shared.global [%0], [%1], 16;" :: "r"(sm), "l"(gm) : "memory")
#define CP_COMMIT() asm volatile("cp.async.commit_group;" ::: "memory")
#define CP_WAIT0()  asm volatile("cp.async.wait_group 0;" ::: "memory")
#define CP_WAIT2()  asm volatile("cp.async.wait_group 2;" ::: "memory")
#define CP_WAIT3()  asm volatile("cp.async.wait_group 3;" ::: "memory")

#define LDMATRIX_X4(r0, r1, r2, r3, addr) \
    asm volatile("ldmatrix.sync.aligned.m8n8.x4.shared.b16 {%0,%1,%2,%3}, [%4];" \
        : "=r"(r0), "=r"(r1), "=r"(r2), "=r"(r3) : "r"(addr))

#define LDMATRIX_X4_T(r0, r1, r2, r3, addr) \
    asm volatile("ldmatrix.sync.aligned.m8n8.x4.trans.shared.b16 {%0,%1,%2,%3}, [%4];" \
        : "=r"(r0), "=r"(r1), "=r"(r2), "=r"(r3) : "r"(addr))

#define MMA_F16(d0, d1, d2, d3, a0, a1, a2, a3, b0, b1) \
    asm volatile("mma.sync.aligned.m16n8k16.row.col.f32.f16.f16.f32 " \
        "{%0,%1,%2,%3}, {%4,%5,%6,%7}, {%8,%9}, {%0,%1,%2,%3};" \
        : "+f"(d0), "+f"(d1), "+f"(d2), "+f"(d3) \
        : "r"(a0), "r"(a1), "r"(a2), "r"(a3), "r"(b0), "r"(b1))

template<typename OutT, int KDIM>
__device__ __forceinline__
void gemm_body(const __half* __restrict__ A,
               const __half* __restrict__ Wt,
               const float* __restrict__ bias,
               OutT* __restrict__ C,
               float cscale)
{
    extern __shared__ __align__(128) char smem[];
    const uint32_t sb = smem_u32(smem);

    const int tid  = threadIdx.x;
    const int wid  = tid >> 5;
    const int lane = tid & 31;
    const int wm   = wid >> 1;
    const int wn   = wid & 1;
    const int g    = lane >> 2;
    const int tg   = lane & 3;

    const int m0 = blockIdx.y * 128;
    const int n0 = blockIdx.x * 128;
    const int NK = KDIM / BK64;

    auto issue_stage = [&](int stage, int kt) {
        const uint32_t sa  = sb + stage * STAGE_B;
        const uint32_t sbf = sa + ATILE_B;
        const __half* gA = A  + (size_t)m0 * KDIM + kt * BK64;
        const __half* gB = Wt + (size_t)n0 * KDIM + kt * BK64;
        #pragma unroll
        for (int i = 0; i < 8; i++) {
            int c = tid + 128 * i;
            int r = c >> 3, s_ = c & 7;
            CP_ASYNC16(sa  + r * (PADK * 2) + s_ * 16, gA + (size_t)r * KDIM + s_ * 8);
            CP_ASYNC16(sbf + r * (PADK * 2) + s_ * 16, gB + (size_t)r * KDIM + s_ * 8);
        }
        CP_COMMIT();
    };

    const int a_row = (lane & 7) + ((lane >> 3) & 1) * 8;
    const int a_k8  = ((lane >> 4) & 1) * 8;
    const int b_row = (lane & 7) + ((lane >> 4) & 1) * 8;
    const int b_k8  = ((lane >> 3) & 1) * 8;

    float acc[4][8][4];
    #pragma unroll
    for (int i = 0; i < 4; i++)
        #pragma unroll
        for (int j = 0; j < 8; j++)
            #pragma unroll
            for (int e = 0; e < 4; e++) acc[i][j][e] = 0.0f;

    issue_stage(0, 0);

    for (int kt = 0; kt < NK; kt++) {
        CP_WAIT0();
        __syncthreads();

        if (kt + 1 < NK) issue_stage((kt + 1) & 1, kt + 1);

        const uint32_t sa  = sb + (kt & 1) * STAGE_B;
        const uint32_t sbf = sa + ATILE_B;

        #pragma unroll
        for (int ks = 0; ks < 4; ks++) {
            const int kcol = ks * 16;
            uint32_t a[4][4];
            #pragma unroll
            for (int mt = 0; mt < 4; mt++) {
                uint32_t ad = sa + (uint32_t)(wm * 64 + mt * 16 + a_row) * (PADK * 2)
                                 + (uint32_t)(kcol + a_k8) * 2;
                LDMATRIX_X4(a[mt][0], a[mt][1], a[mt][2], a[mt][3], ad);
            }
            uint32_t bf[8][2];
            #pragma unroll
            for (int p = 0; p < 4; p++) {
                uint32_t bd = sbf + (uint32_t)(wn * 64 + p * 16 + b_row) * (PADK * 2)
                                  + (uint32_t)(kcol + b_k8) * 2;
                uint32_t x0, x1, x2, x3;
                LDMATRIX_X4(x0, x1, x2, x3, bd);
                bf[p * 2 + 0][0] = x0; bf[p * 2 + 0][1] = x1;
                bf[p * 2 + 1][0] = x2; bf[p * 2 + 1][1] = x3;
            }
            #pragma unroll
            for (int mt = 0; mt < 4; mt++)
                #pragma unroll
                for (int nt = 0; nt < 8; nt++)
                    MMA_F16(acc[mt][nt][0], acc[mt][nt][1], acc[mt][nt][2], acc[mt][nt][3],
                            a[mt][0], a[mt][1], a[mt][2], a[mt][3],
                            bf[nt][0], bf[nt][1]);
        }
    }

    #pragma unroll
    for (int mt = 0; mt < 4; mt++) {
        const int row = m0 + wm * 64 + mt * 16 + g;
        #pragma unroll
        for (int nt = 0; nt < 8; nt++) {
            const int col = n0 + wn * 64 + nt * 8 + tg * 2;
            const float b0 = bias[col], b1 = bias[col + 1];
            float2 v0 = make_float2((acc[mt][nt][0] + b0) * cscale,
                                    (acc[mt][nt][1] + b1) * cscale);
            float2 v1 = make_float2((acc[mt][nt][2] + b0) * cscale,
                                    (acc[mt][nt][3] + b1) * cscale);
            if constexpr (sizeof(OutT) == 4) {
                *(float2*)((float*)C + (size_t)row * D + col)       = v0;
                *(float2*)((float*)C + (size_t)(row + 8) * D + col) = v1;
            } else {
                __half2 h0 = __floats2half2_rn(v0.x, v0.y);
                __half2 h1 = __floats2half2_rn(v1.x, v1.y);
                *(__half2*)((__half*)C + (size_t)row * D + col)       = h0;
                *(__half2*)((__half*)C + (size_t)(row + 8) * D + col) = h1;
            }
        }
    }
}

// Fused Q/K/V projection: one launch, one shared tail.
struct QKVParams {
    const __half* A[3];
    const __half* W[3];
    const float* bias[3];
    __half* C[3];
    float cscale[3];
};

__global__ __launch_bounds__(128, 3)
void gemm_qkv_kernel(QKVParams p)
{
    const int z = blockIdx.z;
    if (z < 2)
        gemm_body<__half, K2>(p.A[z], p.W[z], p.bias[z], p.C[z], p.cscale[z]);
    else
        gemm_body<__half, D>(p.A[2], p.W[2], p.bias[2], p.C[2], p.cscale[2]);
}

__global__ __launch_bounds__(128, 3)
void gemm_out_kernel(const __half* __restrict__ A,
                     const __half* __restrict__ Wt,
                     const float* __restrict__ bias,
                     float* __restrict__ C)
{
    gemm_body<float, D>(A, Wt, bias, C, 1.0f);
}

// ============================================================================
// fp16 HMMA flash attention (R10/R13 winner config, unchanged).
// ============================================================================
static constexpr int AT_SMEM = 18432 * 5;   // Q + 4 KV stages = 92160
static constexpr int PAD64   = 72;
static constexpr uint32_t ONES_H2 = 0x3C003C00u;

__global__ __launch_bounds__(128, 2)
void attn_mma_kernel(const __half* __restrict__ Q,
                     const __half* __restrict__ K,
                     const __half* __restrict__ V,
                     __half* __restrict__ Xh)
{
    extern __shared__ __align__(128) char asmem[];
    const uint32_t sq  = smem_u32(asmem);
    const uint32_t skv = sq + 18432;

    const int tid  = threadIdx.x;
    const int wid  = tid >> 5;
    const int lane = tid & 31;
    const int g    = lane >> 2;
    const int tg   = lane & 3;

    const int b  = blockIdx.z;
    const int h  = blockIdx.y;
    const int q0 = blockIdx.x * 128;

    const int a_row = (lane & 7) + ((lane >> 3) & 1) * 8;
    const int a_k8  = ((lane >> 4) & 1) * 8;
    const int b_row = (lane & 7) + ((lane >> 4) & 1) * 8;
    const int b_k8  = ((lane >> 3) & 1) * 8;
    const int v_row = (lane & 7) + ((lane >> 3) & 1) * 8;
    const int v_d8  = ((lane >> 4) & 1) * 8;

    #pragma unroll
    for (int i = 0; i < 8; i++) {
        int c = tid + 128 * i;
        int r = c >> 3, s_ = c & 7;
        CP_ASYNC16(sq + r * (PAD64 * 2) + s_ * 16,
                   Q + ((size_t)(b * S + q0 + r)) * D + h * DK + s_ * 8);
    }
    CP_COMMIT();

    auto issueKV = [&](int kt, int buf) {
        const uint32_t kb = skv + buf * 18432;
        #pragma unroll
        for (int i = 0; i < 4; i++) {
            int c = tid + 128 * i;
            int r = c >> 3, s_ = c & 7;
            size_t goff = ((size_t)(b * S + kt * 64 + r)) * D + h * DK + s_ * 8;
            CP_ASYNC16(kb + r * (PAD64 * 2) + s_ * 16, K + goff);
            CP_ASYNC16(kb + 9216 + r * (PAD64 * 2) + s_ * 16, V + goff);
        }
        CP_COMMIT();
    };

    issueKV(0, 0);
    issueKV(1, 1);
    issueKV(2, 2);
    CP_WAIT3();                 // Q group complete
    __syncthreads();

    uint32_t qa[2][4][4];
    #pragma unroll
    for (int mf = 0; mf < 2; mf++)
        #pragma unroll
        for (int kc = 0; kc < 4; kc++) {
            uint32_t ad = sq + (uint32_t)(wid * 32 + mf * 16 + a_row) * (PAD64 * 2)
                             + (uint32_t)(kc * 16 + a_k8) * 2;
            LDMATRIX_X4(qa[mf][kc][0], qa[mf][kc][1], qa[mf][kc][2], qa[mf][kc][3], ad);
        }

    float o[2][8][4];
    #pragma unroll
    for (int mf = 0; mf < 2; mf++)
        #pragma unroll
        for (int i = 0; i < 8; i++)
            #pragma unroll
            for (int e = 0; e < 4; e++) o[mf][i][e] = 0.0f;
    float o9[2][4] = {};

    const int NT = S / 64;
    for (int kt = 0; kt < NT; kt++) {
        CP_WAIT2();
        __syncthreads();

        if (kt + 3 < NT) issueKV(kt + 3, (kt + 3) & 3);

        const uint32_t kb = skv + (kt & 3) * 18432;

        float sc[2][8][4];
        #pragma unroll
        for (int mf = 0; mf < 2; mf++)
            #pragma unroll
            for (int i = 0; i < 8; i++)
                #pragma unroll
                for (int e = 0; e < 4; e++) sc[mf][i][e] = 0.0f;

        #pragma unroll
        for (int kc = 0; kc < 4; kc++) {
            uint32_t bfr[8][2];
            #pragma unroll
            for (int p = 0; p < 4; p++) {
                uint32_t bd = kb + (uint32_t)(p * 16 + b_row) * (PAD64 * 2)
                                 + (uint32_t)(kc * 16 + b_k8) * 2;
                uint32_t x0, x1, x2, x3;
                LDMATRIX_X4(x0, x1, x2, x3, bd);
                bfr[p * 2 + 0][0] = x0; bfr[p * 2 + 0][1] = x1;
                bfr[p * 2 + 1][0] = x2; bfr[p * 2 + 1][1] = x3;
            }
            #pragma unroll
            for (int mf = 0; mf < 2; mf++)
                #pragma unroll
                for (int nt = 0; nt < 8; nt++)
                    MMA_F16(sc[mf][nt][0], sc[mf][nt][1], sc[mf][nt][2], sc[mf][nt][3],
                            qa[mf][kc][0], qa[mf][kc][1], qa[mf][kc][2], qa[mf][kc][3],
                            bfr[nt][0], bfr[nt][1]);
        }

        #pragma unroll
        for (int kc = 0; kc < 4; kc++) {
            uint32_t vb[8][2];
            #pragma unroll
            for (int p = 0; p < 4; p++) {
                uint32_t vd = kb + 9216
                            + (uint32_t)(kc * 16 + v_row) * (PAD64 * 2)
                            + (uint32_t)(p * 16 + v_d8) * 2;
                uint32_t x0, x1, x2, x3;
                LDMATRIX_X4_T(x0, x1, x2, x3, vd);
                vb[p * 2 + 0][0] = x0; vb[p * 2 + 0][1] = x1;
                vb[p * 2 + 1][0] = x2; vb[p * 2 + 1][1] = x3;
            }
            #pragma unroll
            for (int mf = 0; mf < 2; mf++) {
                __half2 h0 = __floats2half2_rn(sc[mf][2*kc][0],   sc[mf][2*kc][1]);
                __half2 h1 = __floats2half2_rn(sc[mf][2*kc][2],   sc[mf][2*kc][3]);
                __half2 h2 = __floats2half2_rn(sc[mf][2*kc+1][0], sc[mf][2*kc+1][1]);
                __half2 h3 = __floats2half2_rn(sc[mf][2*kc+1][2], sc[mf][2*kc+1][3]);
                uint32_t pa0 = ex2_h2(*(uint32_t*)&h0);
                uint32_t pa1 = ex2_h2(*(uint32_t*)&h1);
                uint32_t pa2 = ex2_h2(*(uint32_t*)&h2);
                uint32_t pa3 = ex2_h2(*(uint32_t*)&h3);

                #pragma unroll
                for (int nt = 0; nt < 8; nt++)
                    MMA_F16(o[mf][nt][0], o[mf][nt][1], o[mf][nt][2], o[mf][nt][3],
                            pa0, pa1, pa2, pa3, vb[nt][0], vb[nt][1]);
                MMA_F16(o9[mf][0], o9[mf][1], o9[mf][2], o9[mf][3],
                        pa0, pa1, pa2, pa3, ONES_H2, ONES_H2);
            }
        }
    }

    #pragma unroll
    for (int mf = 0; mf < 2; mf++) {
        const float inv0 = 1.0f / o9[mf][0];
        const float inv1 = 1.0f / o9[mf][2];
        const int row0 = q0 + wid * 32 + mf * 16 + g;
        __half* xr0 = Xh + (size_t)(b * S + row0) * D;
        __half* xr1 = Xh + (size_t)(b * S + row0 + 8) * D;
        #pragma unroll
        for (int nt = 0; nt < 8; nt++) {
            const int col = h * DK + nt * 8 + tg * 2;
            *(__half2*)(xr0 + col) =
                __floats2half2_rn(o[mf][nt][0] * inv0, o[mf][nt][1] * inv0);
            *(__half2*)(xr1 + col) =
                __floats2half2_rn(o[mf][nt][2] * inv1, o[mf][nt][3] * inv1);
        }
    }
}

// ----------------------------------------------------------------------------
// Launch
// ----------------------------------------------------------------------------
extern "C" void kernel_launch(void* const* d_in, const int* in_sizes, int n_in,
                              void* d_out, int out_size)
{
    const float* q  = (const float*)d_in[0];
    const float* k  = (const float*)d_in[1];
    const float* v  = (const float*)d_in[2];
    const float* Wq = (const float*)d_in[3];
    const float* bq = (const float*)d_in[4];
    const float* Wk = (const float*)d_in[5];
    const float* bk = (const float*)d_in[6];
    const float* Wv = (const float*)d_in[7];
    const float* bv = (const float*)d_in[8];
    const float* Wo = (const float*)d_in[9];
    const float* bo = (const float*)d_in[10];
    float* out = (float*)d_out;

    __half *Qh, *Kh, *Vh, *Aq, *Ak, *Av, *W2, *WvH, *WoH;
    cudaGetSymbolAddress((void**)&Qh,  g_Qh);
    cudaGetSymbolAddress((void**)&Kh,  g_Kh);
    cudaGetSymbolAddress((void**)&Vh,  g_Vh);
    cudaGetSymbolAddress((void**)&Aq,  g_Aq);
    cudaGetSymbolAddress((void**)&Ak,  g_Ak);
    cudaGetSymbolAddress((void**)&Av,  g_Av);
    cudaGetSymbolAddress((void**)&W2,  g_W2);
    cudaGetSymbolAddress((void**)&WvH, g_WvH);
    cudaGetSymbolAddress((void**)&WoH, g_WoH);
    const size_t WSTRIDE = (size_t)D * K2;

    cudaFuncSetAttribute(gemm_qkv_kernel,
                         cudaFuncAttributeMaxDynamicSharedMemorySize, GEMM_SMEM);
    cudaFuncSetAttribute(gemm_out_kernel,
                         cudaFuncAttributeMaxDynamicSharedMemorySize, GEMM_SMEM);
    cudaFuncSetAttribute(attn_mma_kernel,
                         cudaFuncAttributeMaxDynamicSharedMemorySize, AT_SMEM);

    // All splits, one launch
    SplitAllParams sp;
    sp.asrc[0] = q;  sp.asrc[1] = k;  sp.asrc[2] = v;
    sp.adst[0] = Aq; sp.adst[1] = Ak; sp.adst[2] = Av;
    sp.wsrc[0] = Wq; sp.wsrc[1] = Wk; sp.wsrc[2] = Wv; sp.wsrc[3] = Wo;
    sp.wdst[0] = W2; sp.wdst[1] = W2 + WSTRIDE; sp.wdst[2] = WvH; sp.wdst[3] = WoH;
    split_all_kernel<<<dim3(M, 4), 256>>>(sp);

    // Fused Q/K/V projections, one launch (z<2: K=2048; z=2: K=1024)
    QKVParams gp;
    gp.A[0] = Aq; gp.A[1] = Ak; gp.A[2] = Av;
    gp.W[0] = W2; gp.W[1] = W2 + WSTRIDE; gp.W[2] = WvH;
    gp.bias[0] = bq; gp.bias[1] = bk; gp.bias[2] = bv;
    gp.C[0] = Qh; gp.C[1] = Kh; gp.C[2] = Vh;
    gp.cscale[0] = 0.125f * 1.44269504088896340736f;
    gp.cscale[1] = 1.0f;
    gp.cscale[2] = 1.0f;
    dim3 qkvGrid(D / 128, M / 128, 3);   // (8, 64, 3) = 1536 blocks
    gemm_qkv_kernel<<<qkvGrid, 128, GEMM_SMEM>>>(gp);

    // Attention writes hi-only X (stride D) into g_Aq's storage
    dim3 attnGrid(S / 128, H, B);        // (16, 16, 4)
    attn_mma_kernel<<<attnGrid, 128, AT_SMEM>>>(Qh, Kh, Vh, Aq);

    // Output projection (K=1024, hi-only)
    dim3 outGrid(D / 128, M / 128);      // (8, 64)
    gemm_out_kernel<<<outGrid, 128, GEMM_SMEM>>>(Aq, WoH, bo, out);
}

// round 17
// speedup vs baseline: 1.1452x; 1.1452x over previous
#include <cuda_runtime.h>
#include <cuda_bf16.h>
#include <cuda_fp16.h>
#include <cstdint>
#include <math.h>

// Problem constants
static constexpr int B  = 4;
static constexpr int S  = 2048;
static constexpr int D  = 1024;
static constexpr int H  = 16;
static constexpr int DK = 64;
static constexpr int M  = B * S;      // 8192
static constexpr int K2 = 2 * D;      // 2048: fp16x2 concatenated K

// Scratch (__device__ globals; allocation forbidden)
__device__ __half g_Qh[(size_t)M * D];
__device__ __half g_Kh[(size_t)M * D];
__device__ __half g_Vh[(size_t)M * D];
__device__ __half g_Aq[(size_t)M * K2];      // q split [hi|lo]; reused as attn X (stride D)
__device__ __half g_Ak[(size_t)M * D];       // k hi-only (stride D)
__device__ __half g_Av[(size_t)M * D];       // v hi-only (stride D)
__device__ __half g_Wq2[(size_t)D * K2];     // Wq as [hi|hi] stride K2
__device__ __half g_WkH[(size_t)D * D];      // Wk hi-only, stride D
__device__ __half g_WvH[(size_t)D * D];      // Wv hi-only, stride D
__device__ __half g_WoH[(size_t)D * D];      // Wo hi-only, stride D

__device__ __forceinline__ uint32_t smem_u32(const void* p) {
    uint32_t a;
    asm("{ .reg .u64 t; cvta.to.shared.u64 t, %1; cvt.u32.u64 %0, t; }" : "=r"(a) : "l"(p));
    return a;
}

__device__ __forceinline__ uint32_t ex2_h2(uint32_t x) {
    uint32_t y;
    asm("ex2.approx.f16x2 %0, %1;" : "=r"(y) : "r"(x));
    return y;
}

// ============================================================================
// Splits (separate, homogeneous launches as in R15).
// Activations: q -> [hi|lo] stride K2 ; k,v -> hi only stride D.
// Weights: Wq -> [hi|hi] stride K2 ; Wk/Wv/Wo -> hi only stride D.
// ============================================================================
struct SplitA3Params { const float* src[3]; __half* dst[3]; };

__global__ __launch_bounds__(256)
void split2_a3_kernel(SplitA3Params p)
{
    const int z = blockIdx.y;
    const float* src = p.src[z];
    const int r = blockIdx.x;
    const int c = threadIdx.x * 4;
    float4 x = *(const float4*)(src + (size_t)r * D + c);

    __align__(8) __half h[4];
    float xs[4] = {x.x, x.y, x.z, x.w};
    #pragma unroll
    for (int i = 0; i < 4; i++) h[i] = __float2half_rn(xs[i]);

    if (z == 0) {
        __align__(8) __half l[4];
        #pragma unroll
        for (int i = 0; i < 4; i++)
            l[i] = __float2half_rn(xs[i] - __half2float(h[i]));
        __half* drow = p.dst[0] + (size_t)r * K2;
        *(uint2*)(drow + c)     = *(uint2*)h;
        *(uint2*)(drow + D + c) = *(uint2*)l;
    } else {
        __half* drow = p.dst[z] + (size_t)r * D;
        *(uint2*)(drow + c) = *(uint2*)h;
    }
}

struct SplitW4Params { const float* src[4]; __half* dst[4]; };

__global__ __launch_bounds__(256)
void split2_w4_kernel(SplitW4Params p)
{
    const int w = blockIdx.y;
    const float* src = p.src[w];
    const int r = blockIdx.x;
    const int c = threadIdx.x * 4;
    float4 x = *(const float4*)(src + (size_t)r * D + c);

    __align__(8) __half h[4];
    float xs[4] = {x.x, x.y, x.z, x.w};
    #pragma unroll
    for (int i = 0; i < 4; i++) h[i] = __float2half_rn(xs[i]);

    if (w == 0) {
        // Wq: [hi|hi], stride K2 (pairs with [hi|lo] q activations)
        __half* drow = p.dst[0] + (size_t)r * K2;
        *(uint2*)(drow + c)     = *(uint2*)h;
        *(uint2*)(drow + D + c) = *(uint2*)h;
    } else {
        // Wk, Wv, Wo: hi-only, stride D
        __half* drow = p.dst[w] + (size_t)r * D;
        *(uint2*)(drow + c) = *(uint2*)h;
    }
}

// ============================================================================
// HMMA GEMM: 128x128 block, 4 warps, BK=64, 2-stage cp.async, 3 blocks/SM.
// Templated on KDIM. A and Wt row stride == KDIM.
// ============================================================================
static constexpr int BK64    = 64;
static constexpr int PADK    = 72;
static constexpr int ATILE_B = 128 * PADK * 2;          // 18432
static constexpr int STAGE_B = 2 * ATILE_B;             // 36864
static constexpr int GEMM_SMEM = 2 * STAGE_B;           // 73728 -> 3 blocks/SM

#define CP_ASYNC16(sm, gm) \
    asm volatile("cp.async.cg.shared.global [%0], [%1], 16;" :: "r"(sm), "l"(gm) : "memory")
#define CP_COMMIT() asm volatile("cp.async.commit_group;" ::: "memory")
#define CP_WAIT0()  asm volatile("cp.async.wait_group 0;" ::: "memory")
#define CP_WAIT2()  asm volatile("cp.async.wait_group 2;" ::: "memory")
#define CP_WAIT3()  asm volatile("cp.async.wait_group 3;" ::: "memory")

#define LDMATRIX_X4(r0, r1, r2, r3, addr) \
    asm volatile("ldmatrix.sync.aligned.m8n8.x4.shared.b16 {%0,%1,%2,%3}, [%4];" \
        : "=r"(r0), "=r"(r1), "=r"(r2), "=r"(r3) : "r"(addr))

#define LDMATRIX_X4_T(r0, r1, r2, r3, addr) \
    asm volatile("ldmatrix.sync.aligned.m8n8.x4.trans.shared.b16 {%0,%1,%2,%3}, [%4];" \
        : "=r"(r0), "=r"(r1), "=r"(r2), "=r"(r3) : "r"(addr))

#define MMA_F16(d0, d1, d2, d3, a0, a1, a2, a3, b0, b1) \
    asm volatile("mma.sync.aligned.m16n8k16.row.col.f32.f16.f16.f32 " \
        "{%0,%1,%2,%3}, {%4,%5,%6,%7}, {%8,%9}, {%0,%1,%2,%3};" \
        : "+f"(d0), "+f"(d1), "+f"(d2), "+f"(d3) \
        : "r"(a0), "r"(a1), "r"(a2), "r"(a3), "r"(b0), "r"(b1))

template<typename OutT, int KDIM>
__device__ __forceinline__
void gemm_body(const __half* __restrict__ A,
               const __half* __restrict__ Wt,
               const float* __restrict__ bias,
               OutT* __restrict__ C,
               float cscale)
{
    extern __shared__ __align__(128) char smem[];
    const uint32_t sb = smem_u32(smem);

    const int tid  = threadIdx.x;
    const int wid  = tid >> 5;
    const int lane = tid & 31;
    const int wm   = wid >> 1;
    const int wn   = wid & 1;
    const int g    = lane >> 2;
    const int tg   = lane & 3;

    const int m0 = blockIdx.y * 128;
    const int n0 = blockIdx.x * 128;
    const int NK = KDIM / BK64;

    auto issue_stage = [&](int stage, int kt) {
        const uint32_t sa  = sb + stage * STAGE_B;
        const uint32_t sbf = sa + ATILE_B;
        const __half* gA = A  + (size_t)m0 * KDIM + kt * BK64;
        const __half* gB = Wt + (size_t)n0 * KDIM + kt * BK64;
        #pragma unroll
        for (int i = 0; i < 8; i++) {
            int c = tid + 128 * i;
            int r = c >> 3, s_ = c & 7;
            CP_ASYNC16(sa  + r * (PADK * 2) + s_ * 16, gA + (size_t)r * KDIM + s_ * 8);
            CP_ASYNC16(sbf + r * (PADK * 2) + s_ * 16, gB + (size_t)r * KDIM + s_ * 8);
        }
        CP_COMMIT();
    };

    const int a_row = (lane & 7) + ((lane >> 3) & 1) * 8;
    const int a_k8  = ((lane >> 4) & 1) * 8;
    const int b_row = (lane & 7) + ((lane >> 4) & 1) * 8;
    const int b_k8  = ((lane >> 3) & 1) * 8;

    float acc[4][8][4];
    #pragma unroll
    for (int i = 0; i < 4; i++)
        #pragma unroll
        for (int j = 0; j < 8; j++)
            #pragma unroll
            for (int e = 0; e < 4; e++) acc[i][j][e] = 0.0f;

    issue_stage(0, 0);

    for (int kt = 0; kt < NK; kt++) {
        CP_WAIT0();
        __syncthreads();

        if (kt + 1 < NK) issue_stage((kt + 1) & 1, kt + 1);

        const uint32_t sa  = sb + (kt & 1) * STAGE_B;
        const uint32_t sbf = sa + ATILE_B;

        #pragma unroll
        for (int ks = 0; ks < 4; ks++) {
            const int kcol = ks * 16;
            uint32_t a[4][4];
            #pragma unroll
            for (int mt = 0; mt < 4; mt++) {
                uint32_t ad = sa + (uint32_t)(wm * 64 + mt * 16 + a_row) * (PADK * 2)
                                 + (uint32_t)(kcol + a_k8) * 2;
                LDMATRIX_X4(a[mt][0], a[mt][1], a[mt][2], a[mt][3], ad);
            }
            uint32_t bf[8][2];
            #pragma unroll
            for (int p = 0; p < 4; p++) {
                uint32_t bd = sbf + (uint32_t)(wn * 64 + p * 16 + b_row) * (PADK * 2)
                                  + (uint32_t)(kcol + b_k8) * 2;
                uint32_t x0, x1, x2, x3;
                LDMATRIX_X4(x0, x1, x2, x3, bd);
                bf[p * 2 + 0][0] = x0; bf[p * 2 + 0][1] = x1;
                bf[p * 2 + 1][0] = x2; bf[p * 2 + 1][1] = x3;
            }
            #pragma unroll
            for (int mt = 0; mt < 4; mt++)
                #pragma unroll
                for (int nt = 0; nt < 8; nt++)
                    MMA_F16(acc[mt][nt][0], acc[mt][nt][1], acc[mt][nt][2], acc[mt][nt][3],
                            a[mt][0], a[mt][1], a[mt][2], a[mt][3],
                            bf[nt][0], bf[nt][1]);
        }
    }

    #pragma unroll
    for (int mt = 0; mt < 4; mt++) {
        const int row = m0 + wm * 64 + mt * 16 + g;
        #pragma unroll
        for (int nt = 0; nt < 8; nt++) {
            const int col = n0 + wn * 64 + nt * 8 + tg * 2;
            const float b0 = bias[col], b1 = bias[col + 1];
            float2 v0 = make_float2((acc[mt][nt][0] + b0) * cscale,
                                    (acc[mt][nt][1] + b1) * cscale);
            float2 v1 = make_float2((acc[mt][nt][2] + b0) * cscale,
                                    (acc[mt][nt][3] + b1) * cscale);
            if constexpr (sizeof(OutT) == 4) {
                *(float2*)((float*)C + (size_t)row * D + col)       = v0;
                *(float2*)((float*)C + (size_t)(row + 8) * D + col) = v1;
            } else {
                __half2 h0 = __floats2half2_rn(v0.x, v0.y);
                __half2 h1 = __floats2half2_rn(v1.x, v1.y);
                *(__half2*)((__half*)C + (size_t)row * D + col)       = h0;
                *(__half2*)((__half*)C + (size_t)(row + 8) * D + col) = h1;
            }
        }
    }
}

// Q projection alone (K=2048, fp16x2, scale folded)
__global__ __launch_bounds__(128, 3)
void gemm_q_kernel(const __half* __restrict__ A,
                   const __half* __restrict__ Wt,
                   const float* __restrict__ bias,
                   __half* __restrict__ C,
                   float cscale)
{
    gemm_body<__half, K2>(A, Wt, bias, C, cscale);
}

// K and V projections fused, homogeneous (both K=1024 hi-only)
struct KVParams {
    const __half* A[2];
    const __half* W[2];
    const float* bias[2];
    __half* C[2];
};

__global__ __launch_bounds__(128, 3)
void gemm_kv_kernel(KVParams p)
{
    const int z = blockIdx.z;
    gemm_body<__half, D>(p.A[z], p.W[z], p.bias[z], p.C[z], 1.0f);
}

__global__ __launch_bounds__(128, 3)
void gemm_out_kernel(const __half* __restrict__ A,
                     const __half* __restrict__ Wt,
                     const float* __restrict__ bias,
                     float* __restrict__ C)
{
    gemm_body<float, D>(A, Wt, bias, C, 1.0f);
}

// ============================================================================
// fp16 HMMA flash attention (R10/R13/R15 winner config, unchanged).
// ============================================================================
static constexpr int AT_SMEM = 18432 * 5;   // Q + 4 KV stages = 92160
static constexpr int PAD64   = 72;
static constexpr uint32_t ONES_H2 = 0x3C003C00u;

__global__ __launch_bounds__(128, 2)
void attn_mma_kernel(const __half* __restrict__ Q,
                     const __half* __restrict__ K,
                     const __half* __restrict__ V,
                     __half* __restrict__ Xh)
{
    extern __shared__ __align__(128) char asmem[];
    const uint32_t sq  = smem_u32(asmem);
    const uint32_t skv = sq + 18432;

    const int tid  = threadIdx.x;
    const int wid  = tid >> 5;
    const int lane = tid & 31;
    const int g    = lane >> 2;
    const int tg   = lane & 3;

    const int b  = blockIdx.z;
    const int h  = blockIdx.y;
    const int q0 = blockIdx.x * 128;

    const int a_row = (lane & 7) + ((lane >> 3) & 1) * 8;
    const int a_k8  = ((lane >> 4) & 1) * 8;
    const int b_row = (lane & 7) + ((lane >> 4) & 1) * 8;
    const int b_k8  = ((lane >> 3) & 1) * 8;
    const int v_row = (lane & 7) + ((lane >> 3) & 1) * 8;
    const int v_d8  = ((lane >> 4) & 1) * 8;

    #pragma unroll
    for (int i = 0; i < 8; i++) {
        int c = tid + 128 * i;
        int r = c >> 3, s_ = c & 7;
        CP_ASYNC16(sq + r * (PAD64 * 2) + s_ * 16,
                   Q + ((size_t)(b * S + q0 + r)) * D + h * DK + s_ * 8);
    }
    CP_COMMIT();

    auto issueKV = [&](int kt, int buf) {
        const uint32_t kb = skv + buf * 18432;
        #pragma unroll
        for (int i = 0; i < 4; i++) {
            int c = tid + 128 * i;
            int r = c >> 3, s_ = c & 7;
            size_t goff = ((size_t)(b * S + kt * 64 + r)) * D + h * DK + s_ * 8;
            CP_ASYNC16(kb + r * (PAD64 * 2) + s_ * 16, K + goff);
            CP_ASYNC16(kb + 9216 + r * (PAD64 * 2) + s_ * 16, V + goff);
        }
        CP_COMMIT();
    };

    issueKV(0, 0);
    issueKV(1, 1);
    issueKV(2, 2);
    CP_WAIT3();                 // Q group complete
    __syncthreads();

    uint32_t qa[2][4][4];
    #pragma unroll
    for (int mf = 0; mf < 2; mf++)
        #pragma unroll
        for (int kc = 0; kc < 4; kc++) {
            uint32_t ad = sq + (uint32_t)(wid * 32 + mf * 16 + a_row) * (PAD64 * 2)
                             + (uint32_t)(kc * 16 + a_k8) * 2;
            LDMATRIX_X4(qa[mf][kc][0], qa[mf][kc][1], qa[mf][kc][2], qa[mf][kc][3], ad);
        }

    float o[2][8][4];
    #pragma unroll
    for (int mf = 0; mf < 2; mf++)
        #pragma unroll
        for (int i = 0; i < 8; i++)
            #pragma unroll
            for (int e = 0; e < 4; e++) o[mf][i][e] = 0.0f;
    float o9[2][4] = {};

    const int NT = S / 64;
    for (int kt = 0; kt < NT; kt++) {
        CP_WAIT2();
        __syncthreads();

        if (kt + 3 < NT) issueKV(kt + 3, (kt + 3) & 3);

        const uint32_t kb = skv + (kt & 3) * 18432;

        float sc[2][8][4];
        #pragma unroll
        for (int mf = 0; mf < 2; mf++)
            #pragma unroll
            for (int i = 0; i < 8; i++)
                #pragma unroll
                for (int e = 0; e < 4; e++) sc[mf][i][e] = 0.0f;

        #pragma unroll
        for (int kc = 0; kc < 4; kc++) {
            uint32_t bfr[8][2];
            #pragma unroll
            for (int p = 0; p < 4; p++) {
                uint32_t bd = kb + (uint32_t)(p * 16 + b_row) * (PAD64 * 2)
                                 + (uint32_t)(kc * 16 + b_k8) * 2;
                uint32_t x0, x1, x2, x3;
                LDMATRIX_X4(x0, x1, x2, x3, bd);
                bfr[p * 2 + 0][0] = x0; bfr[p * 2 + 0][1] = x1;
                bfr[p * 2 + 1][0] = x2; bfr[p * 2 + 1][1] = x3;
            }
            #pragma unroll
            for (int mf = 0; mf < 2; mf++)
                #pragma unroll
                for (int nt = 0; nt < 8; nt++)
                    MMA_F16(sc[mf][nt][0], sc[mf][nt][1], sc[mf][nt][2], sc[mf][nt][3],
                            qa[mf][kc][0], qa[mf][kc][1], qa[mf][kc][2], qa[mf][kc][3],
                            bfr[nt][0], bfr[nt][1]);
        }

        #pragma unroll
        for (int kc = 0; kc < 4; kc++) {
            uint32_t vb[8][2];
            #pragma unroll
            for (int p = 0; p < 4; p++) {
                uint32_t vd = kb + 9216
                            + (uint32_t)(kc * 16 + v_row) * (PAD64 * 2)
                            + (uint32_t)(p * 16 + v_d8) * 2;
                uint32_t x0, x1, x2, x3;
                LDMATRIX_X4_T(x0, x1, x2, x3, vd);
                vb[p * 2 + 0][0] = x0; vb[p * 2 + 0][1] = x1;
                vb[p * 2 + 1][0] = x2; vb[p * 2 + 1][1] = x3;
            }
            #pragma unroll
            for (int mf = 0; mf < 2; mf++) {
                __half2 h0 = __floats2half2_rn(sc[mf][2*kc][0],   sc[mf][2*kc][1]);
                __half2 h1 = __floats2half2_rn(sc[mf][2*kc][2],   sc[mf][2*kc][3]);
                __half2 h2 = __floats2half2_rn(sc[mf][2*kc+1][0], sc[mf][2*kc+1][1]);
                __half2 h3 = __floats2half2_rn(sc[mf][2*kc+1][2], sc[mf][2*kc+1][3]);
                uint32_t pa0 = ex2_h2(*(uint32_t*)&h0);
                uint32_t pa1 = ex2_h2(*(uint32_t*)&h1);
                uint32_t pa2 = ex2_h2(*(uint32_t*)&h2);
                uint32_t pa3 = ex2_h2(*(uint32_t*)&h3);

                #pragma unroll
                for (int nt = 0; nt < 8; nt++)
                    MMA_F16(o[mf][nt][0], o[mf][nt][1], o[mf][nt][2], o[mf][nt][3],
                            pa0, pa1, pa2, pa3, vb[nt][0], vb[nt][1]);
                MMA_F16(o9[mf][0], o9[mf][1], o9[mf][2], o9[mf][3],
                        pa0, pa1, pa2, pa3, ONES_H2, ONES_H2);
            }
        }
    }

    #pragma unroll
    for (int mf = 0; mf < 2; mf++) {
        const float inv0 = 1.0f / o9[mf][0];
        const float inv1 = 1.0f / o9[mf][2];
        const int row0 = q0 + wid * 32 + mf * 16 + g;
        __half* xr0 = Xh + (size_t)(b * S + row0) * D;
        __half* xr1 = Xh + (size_t)(b * S + row0 + 8) * D;
        #pragma unroll
        for (int nt = 0; nt < 8; nt++) {
            const int col = h * DK + nt * 8 + tg * 2;
            *(__half2*)(xr0 + col) =
                __floats2half2_rn(o[mf][nt][0] * inv0, o[mf][nt][1] * inv0);
            *(__half2*)(xr1 + col) =
                __floats2half2_rn(o[mf][nt][2] * inv1, o[mf][nt][3] * inv1);
        }
    }
}

// ----------------------------------------------------------------------------
// Launch
// ----------------------------------------------------------------------------
extern "C" void kernel_launch(void* const* d_in, const int* in_sizes, int n_in,
                              void* d_out, int out_size)
{
    const float* q  = (const float*)d_in[0];
    const float* k  = (const float*)d_in[1];
    const float* v  = (const float*)d_in[2];
    const float* Wq = (const float*)d_in[3];
    const float* bq = (const float*)d_in[4];
    const float* Wk = (const float*)d_in[5];
    const float* bk = (const float*)d_in[6];
    const float* Wv = (const float*)d_in[7];
    const float* bv = (const float*)d_in[8];
    const float* Wo = (const float*)d_in[9];
    const float* bo = (const float*)d_in[10];
    float* out = (float*)d_out;

    __half *Qh, *Kh, *Vh, *Aq, *Ak, *Av, *Wq2, *WkH, *WvH, *WoH;
    cudaGetSymbolAddress((void**)&Qh,  g_Qh);
    cudaGetSymbolAddress((void**)&Kh,  g_Kh);
    cudaGetSymbolAddress((void**)&Vh,  g_Vh);
    cudaGetSymbolAddress((void**)&Aq,  g_Aq);
    cudaGetSymbolAddress((void**)&Ak,  g_Ak);
    cudaGetSymbolAddress((void**)&Av,  g_Av);
    cudaGetSymbolAddress((void**)&Wq2, g_Wq2);
    cudaGetSymbolAddress((void**)&WkH, g_WkH);
    cudaGetSymbolAddress((void**)&WvH, g_WvH);
    cudaGetSymbolAddress((void**)&WoH, g_WoH);

    cudaFuncSetAttribute(gemm_q_kernel,
                         cudaFuncAttributeMaxDynamicSharedMemorySize, GEMM_SMEM);
    cudaFuncSetAttribute(gemm_kv_kernel,
                         cudaFuncAttributeMaxDynamicSharedMemorySize, GEMM_SMEM);
    cudaFuncSetAttribute(gemm_out_kernel,
                         cudaFuncAttributeMaxDynamicSharedMemorySize, GEMM_SMEM);
    cudaFuncSetAttribute(attn_mma_kernel,
                         cudaFuncAttributeMaxDynamicSharedMemorySize, AT_SMEM);

    // Split weights (Wq -> [hi|hi] stride K2; Wk/Wv/Wo -> hi-only stride D)
    SplitW4Params wp;
    wp.src[0] = Wq; wp.src[1] = Wk; wp.src[2] = Wv; wp.src[3] = Wo;
    wp.dst[0] = Wq2; wp.dst[1] = WkH; wp.dst[2] = WvH; wp.dst[3] = WoH;
    split2_w4_kernel<<<dim3(D, 4), 256>>>(wp);

    // Split activations (q -> [hi|lo]; k,v -> hi only)
    SplitA3Params ap;
    ap.src[0] = q;  ap.src[1] = k;  ap.src[2] = v;
    ap.dst[0] = Aq; ap.dst[1] = Ak; ap.dst[2] = Av;
    split2_a3_kernel<<<dim3(M, 3), 256>>>(ap);

    // Q projection (K=2048, fp16x2); pre-scaled by log2e/8
    dim3 qGrid(D / 128, M / 128);        // (8, 64)
    gemm_q_kernel<<<qGrid, 128, GEMM_SMEM>>>(Aq, Wq2, bq, Qh,
                                             0.125f * 1.44269504088896340736f);

    // K,V projections fused (both K=1024, hi-only) — homogeneous launch
    KVParams kp;
    kp.A[0] = Ak;  kp.A[1] = Av;
    kp.W[0] = WkH; kp.W[1] = WvH;
    kp.bias[0] = bk; kp.bias[1] = bv;
    kp.C[0] = Kh;  kp.C[1] = Vh;
    dim3 kvGrid(D / 128, M / 128, 2);    // (8, 64, 2)
    gemm_kv_kernel<<<kvGrid, 128, GEMM_SMEM>>>(kp);

    // Attention writes hi-only X (stride D) into g_Aq's storage
    dim3 attnGrid(S / 128, H, B);        // (16, 16, 4)
    attn_mma_kernel<<<attnGrid, 128, AT_SMEM>>>(Qh, Kh, Vh, Aq);

    // Output projection (K=1024, hi-only)
    dim3 outGrid(D / 128, M / 128);      // (8, 64)
    gemm_out_kernel<<<outGrid, 128, GEMM_SMEM>>>(Aq, WoH, bo, out);
}